// round 1
// baseline (speedup 1.0000x reference)
#include <cuda_runtime.h>

#define BB 512
#define DD 512
#define NKB 196

// scratch (no cudaMalloc allowed)
__device__ float g_mem[BB * DD];
__device__ float g_u1[BB * DD];
__device__ float g_u2[BB * DD];

// ---------------------------------------------------------------------------
// Kernel 1: mem[b,i] = sum_k ms[b,k] * Wm[i,k] + bm[i]
// ---------------------------------------------------------------------------
__global__ __launch_bounds__(1024) void mem_gemm_kernel(
    const float* __restrict__ ms, const float* __restrict__ Wm,
    const float* __restrict__ bm, float* __restrict__ mem)
{
    __shared__ float As[32][33];
    __shared__ float Bs[32][33];
    int tx = threadIdx.x, ty = threadIdx.y;
    int b = blockIdx.y * 32 + ty;
    int i = blockIdx.x * 32 + tx;
    float acc = 0.f;
    for (int k0 = 0; k0 < DD; k0 += 32) {
        As[ty][tx] = ms[b * DD + k0 + tx];
        Bs[ty][tx] = Wm[(blockIdx.x * 32 + ty) * DD + k0 + tx];
        __syncthreads();
#pragma unroll
        for (int k = 0; k < 32; k++) acc += As[ty][k] * Bs[tx][k];
        __syncthreads();
    }
    mem[b * DD + i] = acc + bm[i];
}

// ---------------------------------------------------------------------------
// Kernel 2: v[b,e] = sum_d (ctrl[b,d]*W_attn[d]) * W_cat[d,e]   (e in [0,2D))
// epilogue: u1[b,e] = v[b,e]*mem[b,e] (e<D), u2[b,e-D] = v[b,e] (e>=D)
// ---------------------------------------------------------------------------
__global__ __launch_bounds__(1024) void v_gemm_kernel(
    const float* __restrict__ ctrl, const float* __restrict__ Wattn,
    const float* __restrict__ Wcat, const float* __restrict__ mem,
    float* __restrict__ u1, float* __restrict__ u2)
{
    __shared__ float As[32][33];
    __shared__ float Ws[32][33];
    int tx = threadIdx.x, ty = threadIdx.y;
    int b = blockIdx.y * 32 + ty;
    int e = blockIdx.x * 32 + tx;
    float acc = 0.f;
    for (int k0 = 0; k0 < DD; k0 += 32) {
        As[ty][tx] = ctrl[b * DD + k0 + tx] * Wattn[k0 + tx];
        Ws[ty][tx] = Wcat[(size_t)(k0 + ty) * (2 * DD) + e];
        __syncthreads();
#pragma unroll
        for (int k = 0; k < 32; k++) acc += As[ty][k] * Ws[k][tx];
        __syncthreads();
    }
    if (e < DD) u1[b * DD + e] = acc * mem[b * DD + e];
    else        u2[b * DD + (e - DD)] = acc;
}

// ---------------------------------------------------------------------------
// Kernel 3: per-batch attention read.
//   pass1: rai[n] = sum_d u1[d]*kbp[b,d,n] + u2[d]*kb[b,d,n]
//   softmax over n (b_cat / b_attn constants are softmax-invariant, dropped)
//   pass2: out[b,d] = sum_n rvi[n]*kb[b,d,n]
// ---------------------------------------------------------------------------
__global__ __launch_bounds__(256) void attn_read_kernel(
    const float* __restrict__ kb, const float* __restrict__ kbp,
    const float* __restrict__ u1, const float* __restrict__ u2,
    float* __restrict__ out)
{
    __shared__ float su1[DD];
    __shared__ float su2[DD];
    __shared__ float sw[256];   // rvi weights
    __shared__ float red[8];

    const int b   = blockIdx.x;
    const int tid = threadIdx.x;
    const float* kbB  = kb  + (size_t)b * DD * NKB;
    const float* kbpB = kbp + (size_t)b * DD * NKB;

    for (int i = tid; i < DD; i += 256) {
        su1[i] = u1[b * DD + i];
        su2[i] = u2[b * DD + i];
    }
    __syncthreads();

    // ---- pass 1: logits (thread tid owns kb-element n = tid) ----
    float acc = -1e30f;
    if (tid < NKB) {
        acc = 0.f;
#pragma unroll 8
        for (int d = 0; d < DD; d++) {
            acc += su1[d] * kbpB[d * NKB + tid] + su2[d] * kbB[d * NKB + tid];
        }
    }

    // ---- softmax over 196 logits (padded lanes carry -inf / 0) ----
    float m = acc;
#pragma unroll
    for (int o = 16; o > 0; o >>= 1) m = fmaxf(m, __shfl_xor_sync(0xffffffffu, m, o));
    if ((tid & 31) == 0) red[tid >> 5] = m;
    __syncthreads();
    if (tid == 0) {
        float x = red[0];
#pragma unroll
        for (int i = 1; i < 8; i++) x = fmaxf(x, red[i]);
        red[0] = x;
    }
    __syncthreads();
    const float gmax = red[0];
    __syncthreads();

    float e = (tid < NKB) ? __expf(acc - gmax) : 0.f;
    float s = e;
#pragma unroll
    for (int o = 16; o > 0; o >>= 1) s += __shfl_xor_sync(0xffffffffu, s, o);
    if ((tid & 31) == 0) red[tid >> 5] = s;
    __syncthreads();
    if (tid == 0) {
        float x = 0.f;
#pragma unroll
        for (int i = 0; i < 8; i++) x += red[i];
        red[0] = x;
    }
    __syncthreads();
    const float inv = 1.f / red[0];
    sw[tid] = e * inv;
    __syncthreads();

    // ---- pass 2: weighted sum over n, warps own d-rows ----
    const int warp = tid >> 5;
    const int lane = tid & 31;
    for (int d = warp; d < DD; d += 8) {
        const float* row = kbB + (size_t)d * NKB;
        float s2 = 0.f;
        for (int n = lane; n < NKB; n += 32) s2 += row[n] * sw[n];
#pragma unroll
        for (int o = 16; o > 0; o >>= 1) s2 += __shfl_xor_sync(0xffffffffu, s2, o);
        if (lane == 0) out[b * DD + d] = s2;
    }
}

// ---------------------------------------------------------------------------
extern "C" void kernel_launch(void* const* d_in, const int* in_sizes, int n_in,
                              void* d_out, int out_size)
{
    const float* memory_state   = (const float*)d_in[0];  // [B, D]
    const float* knowledge_base = (const float*)d_in[1];  // [B, D, N]
    const float* ctrl_state     = (const float*)d_in[2];  // [B, D]
    const float* kb_proj        = (const float*)d_in[3];  // [B, D, N]
    const float* W_mem          = (const float*)d_in[4];  // [D, D]
    const float* b_mem          = (const float*)d_in[5];  // [D]
    const float* W_cat          = (const float*)d_in[6];  // [D, 2D]
    // d_in[7] = b_cat, d_in[8] = W_attn, d_in[9] = b_attn
    const float* W_attn         = (const float*)d_in[8];  // [1, D]
    float* out = (float*)d_out;                           // [B, D]

    float* mem; cudaGetSymbolAddress((void**)&mem, g_mem);
    float* u1;  cudaGetSymbolAddress((void**)&u1,  g_u1);
    float* u2;  cudaGetSymbolAddress((void**)&u2,  g_u2);

    dim3 blk(32, 32);
    mem_gemm_kernel<<<dim3(DD / 32, BB / 32), blk>>>(memory_state, W_mem, b_mem, mem);
    v_gemm_kernel<<<dim3(2 * DD / 32, BB / 32), blk>>>(ctrl_state, W_attn, W_cat, mem, u1, u2);
    attn_read_kernel<<<BB, 256>>>(knowledge_base, kb_proj, u1, u2, out);
}

// round 2
// speedup vs baseline: 1.7907x; 1.7907x over previous
#include <cuda_runtime.h>

#define BB 512
#define DD 512
#define NN 196
#define TT 14      // n-tile size
#define NTILES 14  // 14*14 = 196
#define PS 15      // padded smem row stride (conflict-free: gcd(15,32)=1)

// scratch (no cudaMalloc allowed)
__device__ float g_mem[BB * DD];
__device__ float g_u1[BB * DD];
__device__ float g_u2[BB * DD];

#define CP_COMMIT() asm volatile("cp.async.commit_group;\n" ::)
#define CP_WAIT1()  asm volatile("cp.async.wait_group 1;\n" ::)
#define CP_WAIT0()  asm volatile("cp.async.wait_group 0;\n" ::)

// ---------------------------------------------------------------------------
// Kernel 1: mem[b,i] = sum_k ms[b,k] * Wm[i,k] + bm[i]
// tile 32(b) x 64(i), 128 threads, 4x4 per thread, k-tile 16
// ---------------------------------------------------------------------------
__global__ __launch_bounds__(128) void mem_gemm_kernel(
    const float* __restrict__ ms, const float* __restrict__ Wm,
    const float* __restrict__ bm, float* __restrict__ mem)
{
    __shared__ float As[16][36];  // [k][row], padded
    __shared__ float Bs[16][68];  // [k][col], padded
    const int t = threadIdx.x;
    const int tx = t & 15, ty = t >> 4;
    const int b0 = blockIdx.y * 32, i0 = blockIdx.x * 64;
    float acc[4][4] = {};

    for (int k0 = 0; k0 < DD; k0 += 16) {
        {   // load A tile 32x16 (one float4 per thread), transpose into smem
            int row = t >> 2, kq = (t & 3) << 2;
            float4 v = *(const float4*)(ms + (b0 + row) * DD + k0 + kq);
            As[kq + 0][row] = v.x; As[kq + 1][row] = v.y;
            As[kq + 2][row] = v.z; As[kq + 3][row] = v.w;
        }
#pragma unroll
        for (int r = 0; r < 2; r++) {  // load W tile 64x16 (2 float4 per thread)
            int idx = t + 128 * r;
            int i = idx >> 2, kq = (idx & 3) << 2;
            float4 v = *(const float4*)(Wm + (i0 + i) * DD + k0 + kq);
            Bs[kq + 0][i] = v.x; Bs[kq + 1][i] = v.y;
            Bs[kq + 2][i] = v.z; Bs[kq + 3][i] = v.w;
        }
        __syncthreads();
#pragma unroll
        for (int k = 0; k < 16; k++) {
            float4 a = *(const float4*)&As[k][ty * 4];
            float4 bv = *(const float4*)&Bs[k][tx * 4];
            float av[4] = {a.x, a.y, a.z, a.w};
            float bb[4] = {bv.x, bv.y, bv.z, bv.w};
#pragma unroll
            for (int r = 0; r < 4; r++)
#pragma unroll
                for (int c = 0; c < 4; c++) acc[r][c] += av[r] * bb[c];
        }
        __syncthreads();
    }
#pragma unroll
    for (int r = 0; r < 4; r++)
#pragma unroll
        for (int c = 0; c < 4; c++)
            mem[(b0 + ty * 4 + r) * DD + i0 + tx * 4 + c] = acc[r][c] + bm[i0 + tx * 4 + c];
}

// ---------------------------------------------------------------------------
// Kernel 2: v[b,f] = sum_k (ctrl[b,k]*Wattn[k]) * Wcat[k,f],  f in [0,2D)
// epilogue: u1 = v[:, :D] * mem,  u2 = v[:, D:]
// tile 32(b) x 128(f), 128 threads, 4x8 per thread, k-tile 16
// ---------------------------------------------------------------------------
__global__ __launch_bounds__(128) void v_gemm_kernel(
    const float* __restrict__ ctrl, const float* __restrict__ Wattn,
    const float* __restrict__ Wcat, const float* __restrict__ mem,
    float* __restrict__ u1, float* __restrict__ u2)
{
    __shared__ float As[16][36];   // [k][row], padded
    __shared__ float Bs[16][128];  // [k][f] — Wcat already k-major, no transpose
    const int t = threadIdx.x;
    const int tx = t & 15, ty = t >> 4;
    const int b0 = blockIdx.y * 32, f0 = blockIdx.x * 128;
    float acc[4][8] = {};

    for (int k0 = 0; k0 < DD; k0 += 16) {
        {   // A = ctrl * Wattn (elementwise), transposed store
            int row = t >> 2, kq = (t & 3) << 2;
            float4 v = *(const float4*)(ctrl + (b0 + row) * DD + k0 + kq);
            float4 w = *(const float4*)(Wattn + k0 + kq);
            As[kq + 0][row] = v.x * w.x; As[kq + 1][row] = v.y * w.y;
            As[kq + 2][row] = v.z * w.z; As[kq + 3][row] = v.w * w.w;
        }
#pragma unroll
        for (int r = 0; r < 4; r++) {  // Wcat tile 16x128 (4 float4 per thread)
            int idx = t + 128 * r;
            int k = idx >> 5, fq = (idx & 31) << 2;
            *(float4*)&Bs[k][fq] = *(const float4*)(Wcat + (size_t)(k0 + k) * (2 * DD) + f0 + fq);
        }
        __syncthreads();
#pragma unroll
        for (int k = 0; k < 16; k++) {
            float4 a = *(const float4*)&As[k][ty * 4];
            float4 p = *(const float4*)&Bs[k][tx * 4];
            float4 q = *(const float4*)&Bs[k][64 + tx * 4];
            float av[4] = {a.x, a.y, a.z, a.w};
            float bb[8] = {p.x, p.y, p.z, p.w, q.x, q.y, q.z, q.w};
#pragma unroll
            for (int r = 0; r < 4; r++)
#pragma unroll
                for (int c = 0; c < 8; c++) acc[r][c] += av[r] * bb[c];
        }
        __syncthreads();
    }
#pragma unroll
    for (int r = 0; r < 4; r++) {
        int b = b0 + ty * 4 + r;
#pragma unroll
        for (int c = 0; c < 8; c++) {
            int f = f0 + ((c < 4) ? (tx * 4 + c) : (64 + tx * 4 + (c - 4)));
            float val = acc[r][c];
            if (f < DD) u1[b * DD + f] = val * mem[b * DD + f];
            else        u2[b * DD + (f - DD)] = val;
        }
    }
}

// ---------------------------------------------------------------------------
// Kernel 3: single-pass flash-style attention read. One block per batch.
// Tiles n into 14x14; each tile staged once in smem (cp.async double-buffer),
// used for both logits and the online-softmax-rescaled output accumulation.
// ---------------------------------------------------------------------------
__device__ __forceinline__ void load_tile(float* buf, const float* kbB,
                                          const float* kbpB, int n0)
{
    const int tid = threadIdx.x;
#pragma unroll
    for (int k = 0; k < 14; k++) {
        int e = tid + (k << 9);           // 0..7167
        int d = e / 14, j = e - d * 14;
        unsigned s1 = (unsigned)__cvta_generic_to_shared(buf + d * PS + j);
        const float* g1 = kbB + d * NN + n0 + j;
        asm volatile("cp.async.ca.shared.global [%0], [%1], 4;\n" :: "r"(s1), "l"(g1));
        unsigned s2 = (unsigned)__cvta_generic_to_shared(buf + DD * PS + d * PS + j);
        const float* g2 = kbpB + d * NN + n0 + j;
        asm volatile("cp.async.ca.shared.global [%0], [%1], 4;\n" :: "r"(s2), "l"(g2));
    }
}

__global__ __launch_bounds__(512) void attn_kernel(
    const float* __restrict__ kb, const float* __restrict__ kbp,
    const float* __restrict__ u1, const float* __restrict__ u2,
    float* __restrict__ out)
{
    extern __shared__ float sm[];
    float* bufs = sm;                        // 2 buffers x (kb 512*15 + kbp 512*15)
    float* su1  = sm + 2 * 2 * DD * PS;      // +30720
    float* su2  = su1 + DD;
    float* slog = su2 + DD;                  // [16]
    float* sexp = slog + 16;                 // [16]
    float* sred = sexp + 16;                 // [0]=scale [1]=tile_sum [2]=Mnew

    const int b = blockIdx.x, tid = threadIdx.x;
    const int w = tid >> 5, lane = tid & 31;
    const float* kbB  = kb  + (size_t)b * DD * NN;
    const float* kbpB = kbp + (size_t)b * DD * NN;

    su1[tid] = u1[b * DD + tid];
    su2[tid] = u2[b * DD + tid];

    load_tile(bufs, kbB, kbpB, 0);
    CP_COMMIT();

    float M = -1e30f, S = 0.f, o = 0.f;

    for (int t = 0; t < NTILES; t++) {
        float* buf = bufs + (t & 1) * (2 * DD * PS);
        if (t + 1 < NTILES) {
            load_tile(bufs + ((t + 1) & 1) * (2 * DD * PS), kbB, kbpB, (t + 1) * TT);
            CP_COMMIT();
            CP_WAIT1();
        } else {
            CP_WAIT0();
        }
        __syncthreads();

        float* kb_s  = buf;
        float* kbp_s = buf + DD * PS;

        // ---- tile logits: warp w computes logit for local n = w ----
        if (w < TT) {
            float p = 0.f;
#pragma unroll 4
            for (int d = lane; d < DD; d += 32)
                p += su1[d] * kbp_s[d * PS + w] + su2[d] * kb_s[d * PS + w];
#pragma unroll
            for (int off = 16; off; off >>= 1) p += __shfl_xor_sync(0xffffffffu, p, off);
            if (!lane) slog[w] = p;
        }
        __syncthreads();

        // ---- warp 0: max / scale / exps / tile-sum, broadcast via smem ----
        if (tid < 32) {
            float l = (lane < TT) ? slog[lane] : -1e30f;
            float mx = l;
#pragma unroll
            for (int off = 16; off; off >>= 1) mx = fmaxf(mx, __shfl_xor_sync(0xffffffffu, mx, off));
            float Mn = fmaxf(M, mx);
            float e = (lane < TT) ? __expf(l - Mn) : 0.f;
            float ts = e;
#pragma unroll
            for (int off = 16; off; off >>= 1) ts += __shfl_xor_sync(0xffffffffu, ts, off);
            if (lane < TT) sexp[lane] = e;
            if (!lane) { sred[0] = __expf(M - Mn); sred[1] = ts; sred[2] = Mn; }
        }
        __syncthreads();

        // ---- online update: thread tid owns output dim d = tid ----
        float scale = sred[0];
        float acc2 = 0.f;
#pragma unroll
        for (int j = 0; j < TT; j++) acc2 += sexp[j] * kb_s[tid * PS + j];
        o = o * scale + acc2;
        S = S * scale + sred[1];
        M = sred[2];
        __syncthreads();   // buffer free before it gets overwritten at t+2 prefetch
    }

    out[b * DD + tid] = o / S;
}

// ---------------------------------------------------------------------------
extern "C" void kernel_launch(void* const* d_in, const int* in_sizes, int n_in,
                              void* d_out, int out_size)
{
    const float* memory_state   = (const float*)d_in[0];  // [B, D]
    const float* knowledge_base = (const float*)d_in[1];  // [B, D, N]
    const float* ctrl_state     = (const float*)d_in[2];  // [B, D]
    const float* kb_proj        = (const float*)d_in[3];  // [B, D, N]
    const float* W_mem          = (const float*)d_in[4];  // [D, D]
    const float* b_mem          = (const float*)d_in[5];  // [D]
    const float* W_cat          = (const float*)d_in[6];  // [D, 2D]
    // d_in[7] = b_cat (softmax-invariant), d_in[9] = b_attn (softmax-invariant)
    const float* W_attn         = (const float*)d_in[8];  // [1, D]
    float* out = (float*)d_out;                           // [B, D]

    float* mem; cudaGetSymbolAddress((void**)&mem, g_mem);
    float* u1;  cudaGetSymbolAddress((void**)&u1,  g_u1);
    float* u2;  cudaGetSymbolAddress((void**)&u2,  g_u2);

    const int smem_bytes = (2 * 2 * DD * PS + 2 * DD + 48) * 4;  // ~127 KB
    cudaFuncSetAttribute(attn_kernel, cudaFuncAttributeMaxDynamicSharedMemorySize, smem_bytes);

    mem_gemm_kernel<<<dim3(DD / 64, BB / 32), 128>>>(memory_state, W_mem, b_mem, mem);
    v_gemm_kernel<<<dim3(2 * DD / 128, BB / 32), 128>>>(ctrl_state, W_attn, W_cat, mem, u1, u2);
    attn_kernel<<<BB, 512, smem_bytes>>>(knowledge_base, kb_proj, u1, u2, out);
}

// round 3
// speedup vs baseline: 2.1460x; 1.1984x over previous
#include <cuda_runtime.h>

#define BB 512
#define DD 512
#define NN 196
#define TT 16          // n-tile width
#define NT 13          // tiles per batch (12 full + 1 of 4 cols)
#define TS 514         // transposed smem row stride in floats (conflict-free)
#define SEG (TT * TS)  // one array buffer = 8224 floats

// scratch (no cudaMalloc allowed)
__device__ float g_mem[BB * DD];
__device__ float g_v1[BB * DD];
__device__ float g_v2[BB * DD];

// ---------------------------------------------------------------------------
// Fused GEMM:  mem = ms @ Wm^T + bm          (f-tiles 0..7)
//              v   = (ctrl*Wattn) @ Wcat     (f-tiles 8..23 -> v1 | v2)
// 64x64 tile, 256 threads, 4x4 per thread, k-tile 16.
// ---------------------------------------------------------------------------
__global__ __launch_bounds__(256) void gemm_kernel(
    const float* __restrict__ ms, const float* __restrict__ Wm,
    const float* __restrict__ bm, const float* __restrict__ ctrl,
    const float* __restrict__ Wattn, const float* __restrict__ Wcat,
    float* __restrict__ memo, float* __restrict__ v1, float* __restrict__ v2)
{
    __shared__ float As[16][68];
    __shared__ float Bs[16][68];
    const int t = threadIdx.x;
    const int tx = t & 15, ty = t >> 4;
    const int b0 = blockIdx.y * 64;
    const bool is_mem = (blockIdx.x < 8);
    const int f0 = is_mem ? blockIdx.x * 64 : (blockIdx.x - 8) * 64;
    const int arow = t >> 2, kq = (t & 3) << 2;
    float acc[4][4] = {};

    for (int k0 = 0; k0 < DD; k0 += 16) {
        float4 av;
        if (is_mem) {
            av = *(const float4*)(ms + (b0 + arow) * DD + k0 + kq);
        } else {
            float4 c4 = *(const float4*)(ctrl + (b0 + arow) * DD + k0 + kq);
            float4 w4 = *(const float4*)(Wattn + k0 + kq);
            av = make_float4(c4.x * w4.x, c4.y * w4.y, c4.z * w4.z, c4.w * w4.w);
        }
        As[kq + 0][arow] = av.x; As[kq + 1][arow] = av.y;
        As[kq + 2][arow] = av.z; As[kq + 3][arow] = av.w;

        if (is_mem) {  // Wm[i][k] -> transpose to Bs[k][i]
            float4 bv = *(const float4*)(Wm + (f0 + arow) * DD + k0 + kq);
            Bs[kq + 0][arow] = bv.x; Bs[kq + 1][arow] = bv.y;
            Bs[kq + 2][arow] = bv.z; Bs[kq + 3][arow] = bv.w;
        } else {       // Wcat[k][f] already k-major
            int kk = t >> 4, fq = (t & 15) << 2;
            *(float4*)&Bs[kk][fq] =
                *(const float4*)(Wcat + (size_t)(k0 + kk) * (2 * DD) + f0 + fq);
        }
        __syncthreads();
#pragma unroll
        for (int k = 0; k < 16; k++) {
            float4 a = *(const float4*)&As[k][ty * 4];
            float4 b = *(const float4*)&Bs[k][tx * 4];
            float aa[4] = {a.x, a.y, a.z, a.w};
            float bb[4] = {b.x, b.y, b.z, b.w};
#pragma unroll
            for (int r = 0; r < 4; r++)
#pragma unroll
                for (int c = 0; c < 4; c++) acc[r][c] += aa[r] * bb[c];
        }
        __syncthreads();
    }

#pragma unroll
    for (int r = 0; r < 4; r++) {
        int b = b0 + ty * 4 + r;
#pragma unroll
        for (int c = 0; c < 4; c++) {
            int f = f0 + tx * 4 + c;
            if (is_mem)        memo[b * DD + f] = acc[r][c] + bm[f];
            else if (f < DD)   v1[b * DD + f] = acc[r][c];
            else               v2[b * DD + (f - DD)] = acc[r][c];
        }
    }
}

// ---------------------------------------------------------------------------
// Persistent flash attention-read. grid=128, block=512, 4 batches per block.
// Tiles staged TRANSPOSED in smem: T[n][d], stride TS=514 -> conflict-free
// STS, conflict-free row reads (logits), conflict-free column reads (output).
// Register-staged prefetch (8 x float4 / thread) pipelines DRAM across tiles
// and batch boundaries.
// ---------------------------------------------------------------------------
__global__ __launch_bounds__(512) void attn_kernel(
    const float* __restrict__ kb, const float* __restrict__ kbp,
    const float* __restrict__ memo, const float* __restrict__ v1,
    const float* __restrict__ v2, float* __restrict__ out)
{
    extern __shared__ float smf[];
    float* su1  = smf + 4 * SEG;
    float* su2  = su1 + DD;
    float* slog = su2 + DD;      // [16]
    float* sexp = slog + 16;     // [16]
    float* sred = sexp + 16;     // [0]=scale [1]=tile_sum [2]=Mnew

    const int tid = threadIdx.x;
    const int w = tid >> 5, lane = tid & 31;
    float4 rkb[4], rkp[4];

    // ---- prefetch step 0 (batch blockIdx.x*4, tile 0) ----
    {
        const float* kbB = kb  + (size_t)(blockIdx.x * 4) * DD * NN;
        const float* kpB = kbp + (size_t)(blockIdx.x * 4) * DD * NN;
        int c4 = (tid & 3) << 2;
#pragma unroll
        for (int i = 0; i < 4; i++) {
            int d = (tid >> 2) + 128 * i;
            rkb[i] = *(const float4*)(kbB + d * NN + c4);
            rkp[i] = *(const float4*)(kpB + d * NN + c4);
        }
    }

    float M = -1e30f, S = 0.f, o = 0.f;
    int phase = 0;

    for (int j = 0; j < 4; j++) {
        const int b = blockIdx.x * 4 + j;
        for (int t = 0; t < NT; t++) {
            float* Tkb = smf + (phase & 1) * 2 * SEG;
            float* Tkp = Tkb + SEG;

            // ---- STS current tile (transposed) ----
            if (t != NT - 1) {
#pragma unroll
                for (int i = 0; i < 4; i++) {
                    int d = (tid >> 2) + 128 * i;
                    float* p1 = Tkb + ((tid & 3) << 2) * TS + d;
                    p1[0] = rkb[i].x; p1[TS] = rkb[i].y;
                    p1[2 * TS] = rkb[i].z; p1[3 * TS] = rkb[i].w;
                    float* p2 = Tkp + ((tid & 3) << 2) * TS + d;
                    p2[0] = rkp[i].x; p2[TS] = rkp[i].y;
                    p2[2 * TS] = rkp[i].z; p2[3 * TS] = rkp[i].w;
                }
            } else {
                Tkb[0 * TS + tid] = rkb[0].x; Tkb[1 * TS + tid] = rkb[0].y;
                Tkb[2 * TS + tid] = rkb[0].z; Tkb[3 * TS + tid] = rkb[0].w;
                Tkp[0 * TS + tid] = rkp[0].x; Tkp[1 * TS + tid] = rkp[0].y;
                Tkp[2 * TS + tid] = rkp[0].z; Tkp[3 * TS + tid] = rkp[0].w;
            }
            __syncthreads();

            if (t == 0) {  // per-batch u vectors: u1 = v1*mem, u2 = v2
                su1[tid] = v1[b * DD + tid] * memo[b * DD + tid];
                su2[tid] = v2[b * DD + tid];
                __syncthreads();
            }

            // ---- prefetch next step (overlaps with compute below) ----
            {
                int ntt = t + 1, nb = b;
                if (ntt == NT) { ntt = 0; nb = b + 1; }
                if (!(j == 3 && t == NT - 1)) {
                    const float* kbB = kb  + (size_t)nb * DD * NN;
                    const float* kpB = kbp + (size_t)nb * DD * NN;
                    if (ntt != NT - 1) {
                        int c4 = (tid & 3) << 2;
#pragma unroll
                        for (int i = 0; i < 4; i++) {
                            int d = (tid >> 2) + 128 * i;
                            rkb[i] = *(const float4*)(kbB + d * NN + TT * ntt + c4);
                            rkp[i] = *(const float4*)(kpB + d * NN + TT * ntt + c4);
                        }
                    } else {
                        rkb[0] = *(const float4*)(kbB + tid * NN + 192);
                        rkp[0] = *(const float4*)(kpB + tid * NN + 192);
                    }
                }
            }

            const int valid = (t != NT - 1) ? TT : 4;

            // ---- logits: warp w -> local n = w (contiguous row reads) ----
            if (w < valid) {
                const float2* rp = (const float2*)(Tkp + w * TS);
                const float2* rb = (const float2*)(Tkb + w * TS);
                const float2* s1 = (const float2*)su1;
                const float2* s2 = (const float2*)su2;
                float p = 0.f;
#pragma unroll
                for (int k2 = 0; k2 < 8; k2++) {
                    int q = lane + (k2 << 5);
                    float2 a = rp[q], bv = rb[q];
                    float2 x1 = s1[q], x2 = s2[q];
                    p += x1.x * a.x + x1.y * a.y + x2.x * bv.x + x2.y * bv.y;
                }
#pragma unroll
                for (int off = 16; off; off >>= 1)
                    p += __shfl_xor_sync(0xffffffffu, p, off);
                if (!lane) slog[w] = p;
            }
            __syncthreads();

            // ---- warp 0: online softmax bookkeeping ----
            if (tid < 32) {
                float l = (lane < valid) ? slog[lane] : -1e30f;
                float mx = l;
#pragma unroll
                for (int off = 16; off; off >>= 1)
                    mx = fmaxf(mx, __shfl_xor_sync(0xffffffffu, mx, off));
                float Mn = fmaxf(M, mx);
                float e = (lane < valid) ? __expf(l - Mn) : 0.f;
                float ts = e;
#pragma unroll
                for (int off = 16; off; off >>= 1)
                    ts += __shfl_xor_sync(0xffffffffu, ts, off);
                if (lane < TT) sexp[lane] = e;
                if (!lane) { sred[0] = __expf(M - Mn); sred[1] = ts; sred[2] = Mn; }
            }
            __syncthreads();

            // ---- output: thread tid owns d=tid (consecutive-lane columns) ----
            const float scale = sred[0];
            float acc2 = 0.f;
#pragma unroll
            for (int jj = 0; jj < TT; jj++) {
                if (jj < valid) acc2 += sexp[jj] * Tkb[jj * TS + tid];
            }
            o = o * scale + acc2;
            S = S * scale + sred[1];
            M = sred[2];
            __syncthreads();
            phase++;
        }
        out[b * DD + tid] = o / S;
        M = -1e30f; S = 0.f; o = 0.f;
    }
}

// ---------------------------------------------------------------------------
extern "C" void kernel_launch(void* const* d_in, const int* in_sizes, int n_in,
                              void* d_out, int out_size)
{
    const float* memory_state   = (const float*)d_in[0];  // [B, D]
    const float* knowledge_base = (const float*)d_in[1];  // [B, D, N]
    const float* ctrl_state     = (const float*)d_in[2];  // [B, D]
    const float* kb_proj        = (const float*)d_in[3];  // [B, D, N]
    const float* W_mem          = (const float*)d_in[4];  // [D, D]
    const float* b_mem          = (const float*)d_in[5];  // [D]
    const float* W_cat          = (const float*)d_in[6];  // [D, 2D]
    // d_in[7] = b_cat, d_in[9] = b_attn: softmax-invariant, dropped exactly
    const float* W_attn         = (const float*)d_in[8];  // [1, D]
    float* out = (float*)d_out;                           // [B, D]

    float* memo; cudaGetSymbolAddress((void**)&memo, g_mem);
    float* v1;   cudaGetSymbolAddress((void**)&v1,  g_v1);
    float* v2;   cudaGetSymbolAddress((void**)&v2,  g_v2);

    const int smem_bytes = (4 * SEG + 2 * DD + 48) * 4;  // ~136 KB
    cudaFuncSetAttribute(attn_kernel, cudaFuncAttributeMaxDynamicSharedMemorySize,
                         smem_bytes);

    gemm_kernel<<<dim3(24, 8), 256>>>(memory_state, W_mem, b_mem,
                                      ctrl_state, W_attn, W_cat, memo, v1, v2);
    attn_kernel<<<128, 512, smem_bytes>>>(knowledge_base, kb_proj,
                                          memo, v1, v2, out);
}